// round 1
// baseline (speedup 1.0000x reference)
#include <cuda_runtime.h>

#define HW   128
#define IMG  (HW*HW)
#define NB   64

typedef unsigned long long u64;

// Scratch buffers (allocation-free rule: __device__ globals)
__device__ float g_bufA[(size_t)NB * 22 * IMG];  // 22-ch concat buffer; x lives in ch 12..21
__device__ float g_bufB[(size_t)NB * 24 * IMG];
__device__ float g_bufC[(size_t)NB * 24 * IMG];

__device__ __forceinline__ u64 pack2(float v) {
    u64 r; unsigned int x = __float_as_uint(v);
    asm("mov.b64 %0, {%1, %1};" : "=l"(r) : "r"(x));
    return r;
}
__device__ __forceinline__ u64 fma2(u64 a, u64 b, u64 c) {
    u64 d;
    asm("fma.rn.f32x2 %0, %1, %2, %3;" : "=l"(d) : "l"(a), "l"(b), "l"(c));
    return d;
}
__device__ __forceinline__ float2 unpack2(u64 v) {
    unsigned int lo, hi;
    asm("mov.b64 {%0, %1}, %2;" : "=r"(lo), "=r"(hi) : "l"(v));
    return make_float2(__uint_as_float(lo), __uint_as_float(hi));
}

// ---------------------------------------------------------------------------
// Fused per-sample 3x3 conv + eval-BN + ReLU.
//   in : [NB, in_nch, 128, 128], uses channels 0..CIN-1
//   w  : wflat[b*wP + wbase + ((o*CIN+i)*9 + ky*3+kx)]
//   out: [NB, out_nch, 128, 128], writes channels 0..COUT-1
// COUT==12 -> 64x32 tile, 8 px/thread; COUT==24 -> 32x32 tile, 4 px/thread.
// ---------------------------------------------------------------------------
template<int CIN, int COUT>
__global__ __launch_bounds__(256)
void conv3x3_bn_relu(const float* __restrict__ in, int in_nch,
                     const float* __restrict__ wflat, int wP, int wbase,
                     const float* __restrict__ gam, const float* __restrict__ bet,
                     const float* __restrict__ mea, const float* __restrict__ varr,
                     int bnoff,
                     float* __restrict__ out, int out_nch)
{
    constexpr int T      = (COUT == 12) ? 8 : 4;
    constexpr int TILE_X = (COUT == 12) ? 64 : 32;
    constexpr int TILE_Y = 32;
    constexpr int TXW    = TILE_X + 2;
    constexpr int TYH    = TILE_Y + 2;
    constexpr int NCH    = (CIN > 12) ? 2 : 1;   // input-channel chunks held in smem
    constexpr int CHUNK  = CIN / NCH;            // 10,12,11,12 -- always exact
    constexpr int U2     = COUT / 2;

    extern __shared__ float smem[];
    float* s_in = smem;                          // CHUNK * TYH * TXW
    float* s_w  = s_in + CHUNK * TYH * TXW;      // CIN * 9 * COUT  (layout [i][k][o])
    float* s_sc = s_w + CIN * 9 * COUT;          // COUT
    float* s_bi = s_sc + COUT;                   // COUT

    const int tid = threadIdx.x;
    const int b   = blockIdx.z;
    const int gx0 = blockIdx.x * TILE_X;
    const int gy0 = blockIdx.y * TILE_Y;

    // --- load + repack weights: [o][i][k] (gmem) -> [i][k][o] (smem) ---
    const float* wsrc = wflat + (size_t)b * wP + wbase;
    for (int idx = tid; idx < CIN * 9 * COUT; idx += 256) {
        int o = idx % COUT;
        int r = idx / COUT;
        int k = r % 9;
        int i = r / 9;
        s_w[idx] = wsrc[(o * CIN + i) * 9 + k];
    }
    if (tid < COUT) {
        float g = gam[bnoff + tid], bb = bet[bnoff + tid];
        float m = mea[bnoff + tid], v  = varr[bnoff + tid];
        float inv = g * rsqrtf(v + 1e-5f);
        s_sc[tid] = inv;
        s_bi[tid] = bb - m * inv;
    }

    const int lane = tid & 31;
    const int warp = tid >> 5;
    int xl, y0;
    if (COUT == 12) { xl = (warp & 1) * 32 + lane; y0 = (warp >> 1) * 8; }
    else            { xl = lane;                   y0 = warp * 4;        }

    u64 acc[T][U2];
    #pragma unroll
    for (int p = 0; p < T; p++)
        #pragma unroll
        for (int u = 0; u < U2; u++) acc[p][u] = 0ull;

    const u64*   w8  = (const u64*)s_w;
    const float* inb = in + (size_t)b * in_nch * IMG;

    for (int ch = 0; ch < NCH; ch++) {
        __syncthreads();
        // --- stage CHUNK input channels (with halo, zero-padded) into smem ---
        for (int idx = tid; idx < CHUNK * TYH * TXW; idx += 256) {
            int c = idx % TXW;
            int r = (idx / TXW) % TYH;
            int i = idx / (TXW * TYH);
            int gy = gy0 - 1 + r, gx = gx0 - 1 + c;
            float v = 0.f;
            if ((unsigned)gy < HW && (unsigned)gx < HW)
                v = inb[(size_t)(ch * CHUNK + i) * IMG + gy * HW + gx];
            s_in[idx] = v;
        }
        __syncthreads();

        #pragma unroll 2
        for (int i = 0; i < CHUNK; i++) {
            const int ii = ch * CHUNK + i;
            #pragma unroll
            for (int k = 0; k < 9; k++) {
                const int ky = k / 3, kx = k % 3;
                u64 wv[U2];
                #pragma unroll
                for (int u = 0; u < U2; u++)
                    wv[u] = w8[(size_t)(ii * 9 + k) * U2 + u];  // uniform broadcast

                const float* row = &s_in[(i * TYH + y0 + ky) * TXW + xl + kx];
                #pragma unroll
                for (int p = 0; p < T; p++) {
                    u64 v2 = pack2(row[p * TXW]);
                    #pragma unroll
                    for (int u = 0; u < U2; u++)
                        acc[p][u] = fma2(v2, wv[u], acc[p][u]);
                }
            }
        }
    }

    // --- epilogue: BN (eval) + ReLU + store ---
    float* ob = out + (size_t)b * out_nch * IMG;
    #pragma unroll
    for (int p = 0; p < T; p++) {
        const int y = gy0 + y0 + p;
        const int x = gx0 + xl;
        float* op = ob + y * HW + x;
        #pragma unroll
        for (int u = 0; u < U2; u++) {
            float2 a = unpack2(acc[p][u]);
            int o0 = 2 * u, o1 = 2 * u + 1;
            float r0 = fmaf(a.x, s_sc[o0], s_bi[o0]);
            float r1 = fmaf(a.y, s_sc[o1], s_bi[o1]);
            op[(size_t)o0 * IMG] = fmaxf(r0, 0.f);
            op[(size_t)o1 * IMG] = fmaxf(r1, 0.f);
        }
    }
}

// ---------------------------------------------------------------------------
// Copy x into channels 12..21 of bufA (makes the dense-skip concat free).
// ---------------------------------------------------------------------------
__global__ void copy_x_kernel(const float* __restrict__ x, float* __restrict__ bufA)
{
    size_t idx = (size_t)blockIdx.x * blockDim.x + threadIdx.x;
    const size_t total = (size_t)NB * 10 * IMG;
    if (idx < total) {
        int p = (int)(idx % IMG);
        int c = (int)((idx / IMG) % 10);
        int b = (int)(idx / ((size_t)IMG * 10));
        bufA[((size_t)b * 22 + 12 + c) * IMG + p] = x[idx];
    }
}

// ---------------------------------------------------------------------------
// Final per-sample 1x1 conv: [B,22,H,W] x [B,11,22] -> [B,11,H,W]
// ---------------------------------------------------------------------------
__global__ __launch_bounds__(256)
void conv1x1_kernel(const float* __restrict__ in, const float* __restrict__ w4,
                    float* __restrict__ out)
{
    __shared__ float s_w[11 * 22];
    const int b   = blockIdx.y;
    const int tid = threadIdx.x;
    if (tid < 242) s_w[tid] = w4[b * 242 + tid];
    __syncthreads();

    const int p0 = blockIdx.x * (256 * 4) + tid;
    const float* inb = in  + (size_t)b * 22 * IMG;
    float*       ob  = out + (size_t)b * 11 * IMG;

    float acc[4][11];
    #pragma unroll
    for (int q = 0; q < 4; q++)
        #pragma unroll
        for (int o = 0; o < 11; o++) acc[q][o] = 0.f;

    #pragma unroll 2
    for (int i = 0; i < 22; i++) {
        float v[4];
        #pragma unroll
        for (int q = 0; q < 4; q++) v[q] = inb[(size_t)i * IMG + p0 + q * 256];
        #pragma unroll
        for (int o = 0; o < 11; o++) {
            float w = s_w[o * 22 + i];
            #pragma unroll
            for (int q = 0; q < 4; q++) acc[q][o] = fmaf(v[q], w, acc[q][o]);
        }
    }
    #pragma unroll
    for (int o = 0; o < 11; o++)
        #pragma unroll
        for (int q = 0; q < 4; q++)
            ob[(size_t)o * IMG + p0 + q * 256] = acc[q][o];
}

// ---------------------------------------------------------------------------

static int smem_bytes(int cin, int cout) {
    int nch   = (cin > 12) ? 2 : 1;
    int chunk = cin / nch;
    int txw   = (cout == 12) ? 66 : 34;
    int tyh   = 34;
    return (chunk * tyh * txw + cin * 9 * cout + 2 * cout) * 4;
}

extern "C" void kernel_launch(void* const* d_in, const int* in_sizes, int n_in,
                              void* d_out, int out_size)
{
    const float* x   = (const float*)d_in[0];
    const float* w1  = (const float*)d_in[1];
    const float* w2  = (const float*)d_in[2];
    const float* w3  = (const float*)d_in[3];
    const float* w4  = (const float*)d_in[4];
    const float* gam = (const float*)d_in[5];
    const float* bet = (const float*)d_in[6];
    const float* mea = (const float*)d_in[7];
    const float* var = (const float*)d_in[8];
    float* out = (float*)d_out;

    float *bufA, *bufB, *bufC;
    cudaGetSymbolAddress((void**)&bufA, g_bufA);
    cudaGetSymbolAddress((void**)&bufB, g_bufB);
    cudaGetSymbolAddress((void**)&bufC, g_bufC);

    // opt-in to >48KB dynamic smem (idempotent; host-side, capture-safe)
    cudaFuncSetAttribute(conv3x3_bn_relu<10,12>, cudaFuncAttributeMaxDynamicSharedMemorySize, smem_bytes(10,12));
    cudaFuncSetAttribute(conv3x3_bn_relu<12,12>, cudaFuncAttributeMaxDynamicSharedMemorySize, smem_bytes(12,12));
    cudaFuncSetAttribute(conv3x3_bn_relu<24,12>, cudaFuncAttributeMaxDynamicSharedMemorySize, smem_bytes(24,12));
    cudaFuncSetAttribute(conv3x3_bn_relu<22,24>, cudaFuncAttributeMaxDynamicSharedMemorySize, smem_bytes(22,24));
    cudaFuncSetAttribute(conv3x3_bn_relu<24,24>, cudaFuncAttributeMaxDynamicSharedMemorySize, smem_bytes(24,24));

    const dim3 g12(2, 4, NB);   // 64x32 tiles
    const dim3 g24(4, 4, NB);   // 32x32 tiles

    // x -> bufA channels 12..21 (skip-concat source, written once per launch)
    copy_x_kernel<<<(NB * 10 * IMG + 255) / 256, 256>>>(x, bufA);

    // ---- stage 1 ----  (BN offsets: 0,12,24)
    conv3x3_bn_relu<10,12><<<g12, 256, smem_bytes(10,12)>>>(x,    10, w1, 3672,    0, gam,bet,mea,var,   0, bufB, 24);
    conv3x3_bn_relu<12,12><<<g12, 256, smem_bytes(12,12)>>>(bufB, 24, w1, 3672, 1080, gam,bet,mea,var,  12, bufC, 24);
    conv3x3_bn_relu<12,12><<<g12, 256, smem_bytes(12,12)>>>(bufC, 24, w1, 3672, 2376, gam,bet,mea,var,  24, bufA, 22);
    // ---- stage 2 ----  (BN offsets: 36,60,84)
    conv3x3_bn_relu<22,24><<<g24, 256, smem_bytes(22,24)>>>(bufA, 22, w2, 12528,    0, gam,bet,mea,var,  36, bufB, 24);
    conv3x3_bn_relu<24,24><<<g24, 256, smem_bytes(24,24)>>>(bufB, 24, w2, 12528, 4752, gam,bet,mea,var,  60, bufC, 24);
    conv3x3_bn_relu<24,12><<<g12, 256, smem_bytes(24,12)>>>(bufC, 24, w2, 12528, 9936, gam,bet,mea,var,  84, bufA, 22);
    // ---- stage 3 ----  (BN offsets: 96,120,144)
    conv3x3_bn_relu<22,24><<<g24, 256, smem_bytes(22,24)>>>(bufA, 22, w3, 12528,    0, gam,bet,mea,var,  96, bufB, 24);
    conv3x3_bn_relu<24,24><<<g24, 256, smem_bytes(24,24)>>>(bufB, 24, w3, 12528, 4752, gam,bet,mea,var, 120, bufC, 24);
    conv3x3_bn_relu<24,12><<<g12, 256, smem_bytes(24,12)>>>(bufC, 24, w3, 12528, 9936, gam,bet,mea,var, 144, bufA, 22);
    // ---- stage 4: 1x1 predictor ----
    conv1x1_kernel<<<dim3(IMG / (256 * 4), NB), 256>>>(bufA, w4, out);
}

// round 2
// speedup vs baseline: 1.0021x; 1.0021x over previous
#include <cuda_runtime.h>

#define HW   128
#define IMG  (HW*HW)
#define NB   64

typedef unsigned long long u64;

// Scratch buffers (allocation-free rule: __device__ globals)
__device__ float g_bufA[(size_t)NB * 22 * IMG];  // 22-ch concat buffer; x lives in ch 12..21
__device__ float g_bufB[(size_t)NB * 24 * IMG];
__device__ float g_bufC[(size_t)NB * 24 * IMG];

__device__ __forceinline__ u64 pack2(float v) {
    u64 r; unsigned int x = __float_as_uint(v);
    asm("mov.b64 %0, {%1, %1};" : "=l"(r) : "r"(x));
    return r;
}
__device__ __forceinline__ u64 fma2(u64 a, u64 b, u64 c) {
    u64 d;
    asm("fma.rn.f32x2 %0, %1, %2, %3;" : "=l"(d) : "l"(a), "l"(b), "l"(c));
    return d;
}
__device__ __forceinline__ float2 unpack2(u64 v) {
    unsigned int lo, hi;
    asm("mov.b64 {%0, %1}, %2;" : "=r"(lo), "=r"(hi) : "l"(v));
    return make_float2(__uint_as_float(lo), __uint_as_float(hi));
}

// ---------------------------------------------------------------------------
// Fused per-sample 3x3 conv + eval-BN + ReLU.
//   in : [NB, in_nch, 128, 128], uses channels 0..CIN-1
//   w  : wflat[b*wP + wbase + ((o*CIN+i)*9 + ky*3+kx)]
//   out: [NB, out_nch, 128, 128], writes channels 0..COUT-1
// COUT==12 -> 64x32 tile, 8 px/thread; COUT==24 -> 32x32 tile, 4 px/thread.
// ---------------------------------------------------------------------------
template<int CIN, int COUT>
__global__ __launch_bounds__(256)
void conv3x3_bn_relu(const float* __restrict__ in, int in_nch,
                     const float* __restrict__ wflat, int wP, int wbase,
                     const float* __restrict__ gam, const float* __restrict__ bet,
                     const float* __restrict__ mea, const float* __restrict__ varr,
                     int bnoff,
                     float* __restrict__ out, int out_nch)
{
    constexpr int T      = (COUT == 12) ? 8 : 4;
    constexpr int TILE_X = (COUT == 12) ? 64 : 32;
    constexpr int TILE_Y = 32;
    constexpr int TXW    = TILE_X + 2;
    constexpr int TYH    = TILE_Y + 2;
    constexpr int NCH    = (CIN > 12) ? 2 : 1;   // input-channel chunks held in smem
    constexpr int CHUNK  = CIN / NCH;            // 10,12,11,12 -- always exact
    constexpr int U2     = COUT / 2;

    extern __shared__ float smem[];
    float* s_in = smem;                          // CHUNK * TYH * TXW
    float* s_w  = s_in + CHUNK * TYH * TXW;      // CIN * 9 * COUT  (layout [i][k][o])
    float* s_sc = s_w + CIN * 9 * COUT;          // COUT
    float* s_bi = s_sc + COUT;                   // COUT

    const int tid = threadIdx.x;
    const int b   = blockIdx.z;
    const int gx0 = blockIdx.x * TILE_X;
    const int gy0 = blockIdx.y * TILE_Y;

    // --- load + repack weights: [o][i][k] (gmem) -> [i][k][o] (smem) ---
    const float* wsrc = wflat + (size_t)b * wP + wbase;
    for (int idx = tid; idx < CIN * 9 * COUT; idx += 256) {
        int o = idx % COUT;
        int r = idx / COUT;
        int k = r % 9;
        int i = r / 9;
        s_w[idx] = wsrc[(o * CIN + i) * 9 + k];
    }
    if (tid < COUT) {
        float g = gam[bnoff + tid], bb = bet[bnoff + tid];
        float m = mea[bnoff + tid], v  = varr[bnoff + tid];
        float inv = g * rsqrtf(v + 1e-5f);
        s_sc[tid] = inv;
        s_bi[tid] = bb - m * inv;
    }

    const int lane = tid & 31;
    const int warp = tid >> 5;
    int xl, y0;
    if (COUT == 12) { xl = (warp & 1) * 32 + lane; y0 = (warp >> 1) * 8; }
    else            { xl = lane;                   y0 = warp * 4;        }

    u64 acc[T][U2];
    #pragma unroll
    for (int p = 0; p < T; p++)
        #pragma unroll
        for (int u = 0; u < U2; u++) acc[p][u] = 0ull;

    const u64*   w8  = (const u64*)s_w;
    const float* inb = in + (size_t)b * in_nch * IMG;

    for (int ch = 0; ch < NCH; ch++) {
        __syncthreads();
        // --- stage CHUNK input channels (with halo, zero-padded) into smem ---
        for (int idx = tid; idx < CHUNK * TYH * TXW; idx += 256) {
            int c = idx % TXW;
            int r = (idx / TXW) % TYH;
            int i = idx / (TXW * TYH);
            int gy = gy0 - 1 + r, gx = gx0 - 1 + c;
            float v = 0.f;
            if ((unsigned)gy < HW && (unsigned)gx < HW)
                v = inb[(size_t)(ch * CHUNK + i) * IMG + gy * HW + gx];
            s_in[idx] = v;
        }
        __syncthreads();

        #pragma unroll 2
        for (int i = 0; i < CHUNK; i++) {
            const int ii = ch * CHUNK + i;
            #pragma unroll
            for (int k = 0; k < 9; k++) {
                const int ky = k / 3, kx = k % 3;
                u64 wv[U2];
                #pragma unroll
                for (int u = 0; u < U2; u++)
                    wv[u] = w8[(size_t)(ii * 9 + k) * U2 + u];  // uniform broadcast

                const float* row = &s_in[(i * TYH + y0 + ky) * TXW + xl + kx];
                #pragma unroll
                for (int p = 0; p < T; p++) {
                    u64 v2 = pack2(row[p * TXW]);
                    #pragma unroll
                    for (int u = 0; u < U2; u++)
                        acc[p][u] = fma2(v2, wv[u], acc[p][u]);
                }
            }
        }
    }

    // --- epilogue: BN (eval) + ReLU + store ---
    float* ob = out + (size_t)b * out_nch * IMG;
    #pragma unroll
    for (int p = 0; p < T; p++) {
        const int y = gy0 + y0 + p;
        const int x = gx0 + xl;
        float* op = ob + y * HW + x;
        #pragma unroll
        for (int u = 0; u < U2; u++) {
            float2 a = unpack2(acc[p][u]);
            int o0 = 2 * u, o1 = 2 * u + 1;
            float r0 = fmaf(a.x, s_sc[o0], s_bi[o0]);
            float r1 = fmaf(a.y, s_sc[o1], s_bi[o1]);
            op[(size_t)o0 * IMG] = fmaxf(r0, 0.f);
            op[(size_t)o1 * IMG] = fmaxf(r1, 0.f);
        }
    }
}

// ---------------------------------------------------------------------------
// Copy x into channels 12..21 of bufA (makes the dense-skip concat free).
// ---------------------------------------------------------------------------
__global__ void copy_x_kernel(const float* __restrict__ x, float* __restrict__ bufA)
{
    size_t idx = (size_t)blockIdx.x * blockDim.x + threadIdx.x;
    const size_t total = (size_t)NB * 10 * IMG;
    if (idx < total) {
        int p = (int)(idx % IMG);
        int c = (int)((idx / IMG) % 10);
        int b = (int)(idx / ((size_t)IMG * 10));
        bufA[((size_t)b * 22 + 12 + c) * IMG + p] = x[idx];
    }
}

// ---------------------------------------------------------------------------
// Final per-sample 1x1 conv: [B,22,H,W] x [B,11,22] -> [B,11,H,W]
// ---------------------------------------------------------------------------
__global__ __launch_bounds__(256)
void conv1x1_kernel(const float* __restrict__ in, const float* __restrict__ w4,
                    float* __restrict__ out)
{
    __shared__ float s_w[11 * 22];
    const int b   = blockIdx.y;
    const int tid = threadIdx.x;
    if (tid < 242) s_w[tid] = w4[b * 242 + tid];
    __syncthreads();

    const int p0 = blockIdx.x * (256 * 4) + tid;
    const float* inb = in  + (size_t)b * 22 * IMG;
    float*       ob  = out + (size_t)b * 11 * IMG;

    float acc[4][11];
    #pragma unroll
    for (int q = 0; q < 4; q++)
        #pragma unroll
        for (int o = 0; o < 11; o++) acc[q][o] = 0.f;

    #pragma unroll 2
    for (int i = 0; i < 22; i++) {
        float v[4];
        #pragma unroll
        for (int q = 0; q < 4; q++) v[q] = inb[(size_t)i * IMG + p0 + q * 256];
        #pragma unroll
        for (int o = 0; o < 11; o++) {
            float w = s_w[o * 22 + i];
            #pragma unroll
            for (int q = 0; q < 4; q++) acc[q][o] = fmaf(v[q], w, acc[q][o]);
        }
    }
    #pragma unroll
    for (int o = 0; o < 11; o++)
        #pragma unroll
        for (int q = 0; q < 4; q++)
            ob[(size_t)o * IMG + p0 + q * 256] = acc[q][o];
}

// ---------------------------------------------------------------------------

static int smem_bytes(int cin, int cout) {
    int nch   = (cin > 12) ? 2 : 1;
    int chunk = cin / nch;
    int txw   = (cout == 12) ? 66 : 34;
    int tyh   = 34;
    return (chunk * tyh * txw + cin * 9 * cout + 2 * cout) * 4;
}

extern "C" void kernel_launch(void* const* d_in, const int* in_sizes, int n_in,
                              void* d_out, int out_size)
{
    const float* x   = (const float*)d_in[0];
    const float* w1  = (const float*)d_in[1];
    const float* w2  = (const float*)d_in[2];
    const float* w3  = (const float*)d_in[3];
    const float* w4  = (const float*)d_in[4];
    const float* gam = (const float*)d_in[5];
    const float* bet = (const float*)d_in[6];
    const float* mea = (const float*)d_in[7];
    const float* var = (const float*)d_in[8];
    float* out = (float*)d_out;

    float *bufA, *bufB, *bufC;
    cudaGetSymbolAddress((void**)&bufA, g_bufA);
    cudaGetSymbolAddress((void**)&bufB, g_bufB);
    cudaGetSymbolAddress((void**)&bufC, g_bufC);

    // opt-in to >48KB dynamic smem (idempotent; host-side, capture-safe)
    cudaFuncSetAttribute(conv3x3_bn_relu<10,12>, cudaFuncAttributeMaxDynamicSharedMemorySize, smem_bytes(10,12));
    cudaFuncSetAttribute(conv3x3_bn_relu<12,12>, cudaFuncAttributeMaxDynamicSharedMemorySize, smem_bytes(12,12));
    cudaFuncSetAttribute(conv3x3_bn_relu<24,12>, cudaFuncAttributeMaxDynamicSharedMemorySize, smem_bytes(24,12));
    cudaFuncSetAttribute(conv3x3_bn_relu<22,24>, cudaFuncAttributeMaxDynamicSharedMemorySize, smem_bytes(22,24));
    cudaFuncSetAttribute(conv3x3_bn_relu<24,24>, cudaFuncAttributeMaxDynamicSharedMemorySize, smem_bytes(24,24));

    const dim3 g12(2, 4, NB);   // 64x32 tiles
    const dim3 g24(4, 4, NB);   // 32x32 tiles

    // x -> bufA channels 12..21 (skip-concat source, written once per launch)
    copy_x_kernel<<<(NB * 10 * IMG + 255) / 256, 256>>>(x, bufA);

    // ---- stage 1 ----  (BN offsets: 0,12,24)
    conv3x3_bn_relu<10,12><<<g12, 256, smem_bytes(10,12)>>>(x,    10, w1, 3672,    0, gam,bet,mea,var,   0, bufB, 24);
    conv3x3_bn_relu<12,12><<<g12, 256, smem_bytes(12,12)>>>(bufB, 24, w1, 3672, 1080, gam,bet,mea,var,  12, bufC, 24);
    conv3x3_bn_relu<12,12><<<g12, 256, smem_bytes(12,12)>>>(bufC, 24, w1, 3672, 2376, gam,bet,mea,var,  24, bufA, 22);
    // ---- stage 2 ----  (BN offsets: 36,60,84)
    conv3x3_bn_relu<22,24><<<g24, 256, smem_bytes(22,24)>>>(bufA, 22, w2, 12528,    0, gam,bet,mea,var,  36, bufB, 24);
    conv3x3_bn_relu<24,24><<<g24, 256, smem_bytes(24,24)>>>(bufB, 24, w2, 12528, 4752, gam,bet,mea,var,  60, bufC, 24);
    conv3x3_bn_relu<24,12><<<g12, 256, smem_bytes(24,12)>>>(bufC, 24, w2, 12528, 9936, gam,bet,mea,var,  84, bufA, 22);
    // ---- stage 3 ----  (BN offsets: 96,120,144)
    conv3x3_bn_relu<22,24><<<g24, 256, smem_bytes(22,24)>>>(bufA, 22, w3, 12528,    0, gam,bet,mea,var,  96, bufB, 24);
    conv3x3_bn_relu<24,24><<<g24, 256, smem_bytes(24,24)>>>(bufB, 24, w3, 12528, 4752, gam,bet,mea,var, 120, bufC, 24);
    conv3x3_bn_relu<24,12><<<g12, 256, smem_bytes(24,12)>>>(bufC, 24, w3, 12528, 9936, gam,bet,mea,var, 144, bufA, 22);
    // ---- stage 4: 1x1 predictor ----
    conv1x1_kernel<<<dim3(IMG / (256 * 4), NB), 256>>>(bufA, w4, out);
}

// round 3
// speedup vs baseline: 1.1492x; 1.1469x over previous
#include <cuda_runtime.h>

#define HW   128
#define IMG  (HW*HW)
#define NB   64

typedef unsigned long long u64;

// Scratch buffers (allocation-free rule: __device__ globals)
__device__ float g_bufA[(size_t)NB * 22 * IMG];  // 22-ch concat buffer; x lives in ch 12..21
__device__ float g_bufB[(size_t)NB * 24 * IMG];
__device__ float g_bufC[(size_t)NB * 24 * IMG];

__device__ __forceinline__ u64 pack2(float v) {
    u64 r; unsigned int x = __float_as_uint(v);
    asm("mov.b64 %0, {%1, %1};" : "=l"(r) : "r"(x));
    return r;
}
__device__ __forceinline__ u64 fma2(u64 a, u64 b, u64 c) {
    u64 d;
    asm("fma.rn.f32x2 %0, %1, %2, %3;" : "=l"(d) : "l"(a), "l"(b), "l"(c));
    return d;
}
__device__ __forceinline__ float2 unpack2(u64 v) {
    unsigned int lo, hi;
    asm("mov.b64 {%0, %1}, %2;" : "=r"(lo), "=r"(hi) : "l"(v));
    return make_float2(__uint_as_float(lo), __uint_as_float(hi));
}

// ---------------------------------------------------------------------------
// Fused per-sample 3x3 conv + eval-BN + ReLU, 12 output channels per CTA.
// Tile 64x16, T=4 rows/thread, 256 threads, 2 CTAs/SM.
// 24-out layers are split into two output halves via gridDim.x (blockIdx.x&... ):
//   tile_x = blockIdx.x >> (nh-1 ? 1 : 0) -- encoded as: half = bx & (nh-1)
// Weights gmem layout: wflat[b*wP + wbase + ((o*CIN + i)*9 + k)], o is GLOBAL
// out-channel; the kernel adds ochoff internally.
// ---------------------------------------------------------------------------
template<int CIN, int NHALF>
__global__ __launch_bounds__(256, 2)
void conv3x3_bn_relu12(const float* __restrict__ in, int in_nch,
                       const float* __restrict__ wflat, int wP, int wbase,
                       const float* __restrict__ gam, const float* __restrict__ bet,
                       const float* __restrict__ mea, const float* __restrict__ varr,
                       int bnoff,
                       float* __restrict__ out, int out_nch)
{
    constexpr int COUT   = 12;
    constexpr int U2     = 6;
    constexpr int T      = 4;
    constexpr int TILE_X = 64;
    constexpr int TILE_Y = 16;
    constexpr int TXW    = TILE_X + 2;   // 66
    constexpr int TYH    = TILE_Y + 2;   // 18
    constexpr int NCH    = (CIN > 12) ? 2 : 1;
    constexpr int CHUNK  = CIN / NCH;    // 10,12,11,12

    extern __shared__ float smem[];
    float* s_in = smem;                          // CHUNK * TYH * TXW
    float* s_w  = s_in + CHUNK * TYH * TXW;      // CIN * 9 * 12  (layout [i][k][o])
    float* s_sc = s_w + CIN * 9 * COUT;          // 12
    float* s_bi = s_sc + COUT;                   // 12

    const int tid  = threadIdx.x;
    const int b    = blockIdx.z;
    const int half   = blockIdx.x & (NHALF - 1);
    const int ochoff = half * 12;
    const int gx0  = (blockIdx.x / NHALF) * TILE_X;
    const int gy0  = blockIdx.y * TILE_Y;

    // --- load + repack weights: [o][i][k] (gmem) -> [i][k][o] (smem) ---
    const float* wsrc = wflat + (size_t)b * wP + wbase + (size_t)ochoff * CIN * 9;
    for (int idx = tid; idx < CIN * 9 * COUT; idx += 256) {
        int o = idx % COUT;
        int r = idx / COUT;
        int k = r % 9;
        int i = r / 9;
        s_w[idx] = wsrc[(o * CIN + i) * 9 + k];
    }
    if (tid < COUT) {
        int c = bnoff + ochoff + tid;
        float g = gam[c], bb = bet[c], m = mea[c], v = varr[c];
        float inv = g * rsqrtf(v + 1e-5f);
        s_sc[tid] = inv;
        s_bi[tid] = bb - m * inv;
    }

    const int lane = tid & 31;
    const int warp = tid >> 5;
    const int xl   = (warp & 1) * 32 + lane;   // 0..63
    const int y0   = (warp >> 1) * T;          // 0,4,8,12

    u64 acc[T][U2];
    #pragma unroll
    for (int p = 0; p < T; p++)
        #pragma unroll
        for (int u = 0; u < U2; u++) acc[p][u] = 0ull;

    const u64*   w8  = (const u64*)s_w;
    const float* inb = in + (size_t)b * in_nch * IMG;

    for (int ch = 0; ch < NCH; ch++) {
        __syncthreads();
        // --- stage CHUNK input channels (with halo, zero-padded) into smem ---
        for (int idx = tid; idx < CHUNK * TYH * TXW; idx += 256) {
            int c = idx % TXW;
            int r = (idx / TXW) % TYH;
            int i = idx / (TXW * TYH);
            int gy = gy0 - 1 + r, gx = gx0 - 1 + c;
            float v = 0.f;
            if ((unsigned)gy < HW && (unsigned)gx < HW)
                v = inb[(size_t)(ch * CHUNK + i) * IMG + gy * HW + gx];
            s_in[idx] = v;
        }
        __syncthreads();

        #pragma unroll 2
        for (int i = 0; i < CHUNK; i++) {
            const int ii = ch * CHUNK + i;
            const float* srow = &s_in[(i * TYH + y0) * TXW + xl];
            #pragma unroll
            for (int kx = 0; kx < 3; kx++) {
                // load the T+2 rows this thread needs, once per kx
                u64 vr[T + 2];
                #pragma unroll
                for (int r = 0; r < T + 2; r++)
                    vr[r] = pack2(srow[r * TXW + kx]);
                #pragma unroll
                for (int ky = 0; ky < 3; ky++) {
                    u64 wv[U2];
                    #pragma unroll
                    for (int u = 0; u < U2; u++)
                        wv[u] = w8[(size_t)(ii * 9 + ky * 3 + kx) * U2 + u];  // broadcast
                    #pragma unroll
                    for (int p = 0; p < T; p++)
                        #pragma unroll
                        for (int u = 0; u < U2; u++)
                            acc[p][u] = fma2(vr[p + ky], wv[u], acc[p][u]);
                }
            }
        }
    }

    // --- epilogue: BN (eval) + ReLU + store ---
    float* ob = out + (size_t)b * out_nch * IMG + (size_t)ochoff * IMG;
    #pragma unroll
    for (int p = 0; p < T; p++) {
        const int y = gy0 + y0 + p;
        const int x = gx0 + xl;
        float* op = ob + y * HW + x;
        #pragma unroll
        for (int u = 0; u < U2; u++) {
            float2 a = unpack2(acc[p][u]);
            int o0 = 2 * u, o1 = 2 * u + 1;
            float r0 = fmaf(a.x, s_sc[o0], s_bi[o0]);
            float r1 = fmaf(a.y, s_sc[o1], s_bi[o1]);
            op[(size_t)o0 * IMG] = fmaxf(r0, 0.f);
            op[(size_t)o1 * IMG] = fmaxf(r1, 0.f);
        }
    }
}

// ---------------------------------------------------------------------------
// Copy x into channels 12..21 of bufA (makes the dense-skip concat free).
// ---------------------------------------------------------------------------
__global__ void copy_x_kernel(const float* __restrict__ x, float* __restrict__ bufA)
{
    size_t idx = (size_t)blockIdx.x * blockDim.x + threadIdx.x;
    const size_t total = (size_t)NB * 10 * IMG;
    if (idx < total) {
        int p = (int)(idx % IMG);
        int c = (int)((idx / IMG) % 10);
        int b = (int)(idx / ((size_t)IMG * 10));
        bufA[((size_t)b * 22 + 12 + c) * IMG + p] = x[idx];
    }
}

// ---------------------------------------------------------------------------
// Final per-sample 1x1 conv: [B,22,H,W] x [B,11,22] -> [B,11,H,W]
// ---------------------------------------------------------------------------
__global__ __launch_bounds__(256)
void conv1x1_kernel(const float* __restrict__ in, const float* __restrict__ w4,
                    float* __restrict__ out)
{
    __shared__ float s_w[11 * 22];
    const int b   = blockIdx.y;
    const int tid = threadIdx.x;
    if (tid < 242) s_w[tid] = w4[b * 242 + tid];
    __syncthreads();

    const int p0 = blockIdx.x * (256 * 4) + tid;
    const float* inb = in  + (size_t)b * 22 * IMG;
    float*       ob  = out + (size_t)b * 11 * IMG;

    float acc[4][11];
    #pragma unroll
    for (int q = 0; q < 4; q++)
        #pragma unroll
        for (int o = 0; o < 11; o++) acc[q][o] = 0.f;

    #pragma unroll 2
    for (int i = 0; i < 22; i++) {
        float v[4];
        #pragma unroll
        for (int q = 0; q < 4; q++) v[q] = inb[(size_t)i * IMG + p0 + q * 256];
        #pragma unroll
        for (int o = 0; o < 11; o++) {
            float w = s_w[o * 22 + i];
            #pragma unroll
            for (int q = 0; q < 4; q++) acc[q][o] = fmaf(v[q], w, acc[q][o]);
        }
    }
    #pragma unroll
    for (int o = 0; o < 11; o++)
        #pragma unroll
        for (int q = 0; q < 4; q++)
            ob[(size_t)o * IMG + p0 + q * 256] = acc[q][o];
}

// ---------------------------------------------------------------------------

static int smem_bytes(int cin) {
    int nch   = (cin > 12) ? 2 : 1;
    int chunk = cin / nch;
    return (chunk * 18 * 66 + cin * 9 * 12 + 24) * 4;
}

extern "C" void kernel_launch(void* const* d_in, const int* in_sizes, int n_in,
                              void* d_out, int out_size)
{
    const float* x   = (const float*)d_in[0];
    const float* w1  = (const float*)d_in[1];
    const float* w2  = (const float*)d_in[2];
    const float* w3  = (const float*)d_in[3];
    const float* w4  = (const float*)d_in[4];
    const float* gam = (const float*)d_in[5];
    const float* bet = (const float*)d_in[6];
    const float* mea = (const float*)d_in[7];
    const float* var = (const float*)d_in[8];
    float* out = (float*)d_out;

    float *bufA, *bufB, *bufC;
    cudaGetSymbolAddress((void**)&bufA, g_bufA);
    cudaGetSymbolAddress((void**)&bufB, g_bufB);
    cudaGetSymbolAddress((void**)&bufC, g_bufC);

    // opt-in to >48KB dynamic smem (idempotent; host-side, capture-safe)
    cudaFuncSetAttribute(conv3x3_bn_relu12<10,1>, cudaFuncAttributeMaxDynamicSharedMemorySize, smem_bytes(10));
    cudaFuncSetAttribute(conv3x3_bn_relu12<12,1>, cudaFuncAttributeMaxDynamicSharedMemorySize, smem_bytes(12));
    cudaFuncSetAttribute(conv3x3_bn_relu12<22,2>, cudaFuncAttributeMaxDynamicSharedMemorySize, smem_bytes(22));
    cudaFuncSetAttribute(conv3x3_bn_relu12<24,2>, cudaFuncAttributeMaxDynamicSharedMemorySize, smem_bytes(24));
    cudaFuncSetAttribute(conv3x3_bn_relu12<24,1>, cudaFuncAttributeMaxDynamicSharedMemorySize, smem_bytes(24));

    const dim3 g1(2, 8, NB);   // 12-out layers: 2 x-tiles
    const dim3 g2(4, 8, NB);   // 24-out layers: 2 x-tiles * 2 output halves

    // x -> bufA channels 12..21 (skip-concat source, written once per launch)
    copy_x_kernel<<<(NB * 10 * IMG + 255) / 256, 256>>>(x, bufA);

    // ---- stage 1 ----  (BN offsets: 0,12,24)
    conv3x3_bn_relu12<10,1><<<g1, 256, smem_bytes(10)>>>(x,    10, w1, 3672,    0, gam,bet,mea,var,   0, bufB, 24);
    conv3x3_bn_relu12<12,1><<<g1, 256, smem_bytes(12)>>>(bufB, 24, w1, 3672, 1080, gam,bet,mea,var,  12, bufC, 24);
    conv3x3_bn_relu12<12,1><<<g1, 256, smem_bytes(12)>>>(bufC, 24, w1, 3672, 2376, gam,bet,mea,var,  24, bufA, 22);
    // ---- stage 2 ----  (BN offsets: 36,60,84)
    conv3x3_bn_relu12<22,2><<<g2, 256, smem_bytes(22)>>>(bufA, 22, w2, 12528,    0, gam,bet,mea,var,  36, bufB, 24);
    conv3x3_bn_relu12<24,2><<<g2, 256, smem_bytes(24)>>>(bufB, 24, w2, 12528, 4752, gam,bet,mea,var,  60, bufC, 24);
    conv3x3_bn_relu12<24,1><<<g1, 256, smem_bytes(24)>>>(bufC, 24, w2, 12528, 9936, gam,bet,mea,var,  84, bufA, 22);
    // ---- stage 3 ----  (BN offsets: 96,120,144)
    conv3x3_bn_relu12<22,2><<<g2, 256, smem_bytes(22)>>>(bufA, 22, w3, 12528,    0, gam,bet,mea,var,  96, bufB, 24);
    conv3x3_bn_relu12<24,2><<<g2, 256, smem_bytes(24)>>>(bufB, 24, w3, 12528, 4752, gam,bet,mea,var, 120, bufC, 24);
    conv3x3_bn_relu12<24,1><<<g1, 256, smem_bytes(24)>>>(bufC, 24, w3, 12528, 9936, gam,bet,mea,var, 144, bufA, 22);
    // ---- stage 4: 1x1 predictor ----
    conv1x1_kernel<<<dim3(IMG / (256 * 4), NB), 256>>>(bufA, w4, out);
}

// round 4
// speedup vs baseline: 1.3419x; 1.1677x over previous
#include <cuda_runtime.h>

#define HW   128
#define IMG  (HW*HW)
#define NB   64

typedef unsigned long long u64;

// Scratch buffers (allocation-free rule: __device__ globals)
__device__ float g_bufA[(size_t)NB * 22 * IMG];  // 22-ch concat buffer; x lives in ch 12..21
__device__ float g_bufB[(size_t)NB * 24 * IMG];
__device__ float g_bufC[(size_t)NB * 24 * IMG];

__device__ __forceinline__ u64 pack2(float v) {
    u64 r; unsigned int x = __float_as_uint(v);
    asm("mov.b64 %0, {%1, %1};" : "=l"(r) : "r"(x));
    return r;
}
__device__ __forceinline__ u64 fma2(u64 a, u64 b, u64 c) {
    u64 d;
    asm("fma.rn.f32x2 %0, %1, %2, %3;" : "=l"(d) : "l"(a), "l"(b), "l"(c));
    return d;
}
__device__ __forceinline__ float2 unpack2(u64 v) {
    unsigned int lo, hi;
    asm("mov.b64 {%0, %1}, %2;" : "=r"(lo), "=r"(hi) : "l"(v));
    return make_float2(__uint_as_float(lo), __uint_as_float(hi));
}

// ---------------------------------------------------------------------------
// Fused per-sample 3x3 conv + eval-BN + ReLU, 12 output channels per CTA.
// 128 threads, tile 64x8, T=4 rows/thread, 5 CTAs/SM (20 warps).
// Weights staged in smem as [i][k][o] so each (i,k) is a contiguous 48B run,
// loaded with 3x LDS.128 uniform broadcasts.
// 24-out layers split into two output halves via gridDim.x (NHALF=2).
// ---------------------------------------------------------------------------
template<int CIN, int NHALF>
__global__ __launch_bounds__(128, 5)
void conv3x3_bn_relu12(const float* __restrict__ in, int in_nch,
                       const float* __restrict__ wflat, int wP, int wbase,
                       const float* __restrict__ gam, const float* __restrict__ bet,
                       const float* __restrict__ mea, const float* __restrict__ varr,
                       int bnoff,
                       float* __restrict__ out, int out_nch)
{
    constexpr int COUT   = 12;
    constexpr int U2     = 6;
    constexpr int T      = 4;
    constexpr int TILE_X = 64;
    constexpr int TILE_Y = 8;
    constexpr int TXW    = TILE_X + 2;   // 66
    constexpr int TYH    = TILE_Y + 2;   // 10
    constexpr int NCH    = (CIN > 12) ? 2 : 1;
    constexpr int CHUNK  = CIN / NCH;    // 10,12,11,12
    constexpr int NT     = 128;

    extern __shared__ float smem[];
    float* s_in = smem;                          // CHUNK * TYH * TXW
    float* s_w  = s_in + CHUNK * TYH * TXW;      // CIN * 9 * 12  (layout [i][k][o])
    float* s_sc = s_w + CIN * 9 * COUT;          // 12
    float* s_bi = s_sc + COUT;                   // 12

    const int tid  = threadIdx.x;
    const int b    = blockIdx.z;
    const int half   = blockIdx.x & (NHALF - 1);
    const int ochoff = half * 12;
    const int gx0  = (blockIdx.x / NHALF) * TILE_X;
    const int gy0  = blockIdx.y * TILE_Y;

    // --- load + repack weights: [o][i][k] (gmem) -> [i][k][o] (smem) ---
    const float* wsrc = wflat + (size_t)b * wP + wbase + (size_t)ochoff * CIN * 9;
    for (int idx = tid; idx < CIN * 9 * COUT; idx += NT) {
        int o = idx % COUT;
        int r = idx / COUT;
        int k = r % 9;
        int i = r / 9;
        s_w[idx] = wsrc[(o * CIN + i) * 9 + k];
    }
    if (tid < COUT) {
        int c = bnoff + ochoff + tid;
        float g = gam[c], bb = bet[c], m = mea[c], v = varr[c];
        float inv = g * rsqrtf(v + 1e-5f);
        s_sc[tid] = inv;
        s_bi[tid] = bb - m * inv;
    }

    const int lane = tid & 31;
    const int warp = tid >> 5;
    const int xl   = (warp & 1) * 32 + lane;   // 0..63
    const int y0   = (warp >> 1) * T;          // 0,4

    u64 acc[T][U2];
    #pragma unroll
    for (int p = 0; p < T; p++)
        #pragma unroll
        for (int u = 0; u < U2; u++) acc[p][u] = 0ull;

    const ulonglong2* w16 = (const ulonglong2*)s_w;   // 3 vec per (i,k)
    const float* inb = in + (size_t)b * in_nch * IMG;

    for (int ch = 0; ch < NCH; ch++) {
        __syncthreads();
        // --- stage CHUNK input channels (with halo, zero-padded) into smem ---
        for (int idx = tid; idx < CHUNK * TYH * TXW; idx += NT) {
            int c = idx % TXW;
            int r = (idx / TXW) % TYH;
            int i = idx / (TXW * TYH);
            int gy = gy0 - 1 + r, gx = gx0 - 1 + c;
            float v = 0.f;
            if ((unsigned)gy < HW && (unsigned)gx < HW)
                v = inb[(size_t)(ch * CHUNK + i) * IMG + gy * HW + gx];
            s_in[idx] = v;
        }
        __syncthreads();

        #pragma unroll 2
        for (int i = 0; i < CHUNK; i++) {
            const int ii = ch * CHUNK + i;
            const float* srow = &s_in[(i * TYH + y0) * TXW + xl];
            #pragma unroll
            for (int kx = 0; kx < 3; kx++) {
                // load the T+2 rows this thread needs, once per kx
                u64 vr[T + 2];
                #pragma unroll
                for (int r = 0; r < T + 2; r++)
                    vr[r] = pack2(srow[r * TXW + kx]);
                #pragma unroll
                for (int ky = 0; ky < 3; ky++) {
                    // 12 out-channel weights for (ii, ky, kx): 3x LDS.128 broadcast
                    const ulonglong2* wp = &w16[(size_t)(ii * 9 + ky * 3 + kx) * 3];
                    u64 wv[U2];
                    ulonglong2 w0 = wp[0], w1 = wp[1], w2 = wp[2];
                    wv[0] = w0.x; wv[1] = w0.y;
                    wv[2] = w1.x; wv[3] = w1.y;
                    wv[4] = w2.x; wv[5] = w2.y;
                    #pragma unroll
                    for (int p = 0; p < T; p++)
                        #pragma unroll
                        for (int u = 0; u < U2; u++)
                            acc[p][u] = fma2(vr[p + ky], wv[u], acc[p][u]);
                }
            }
        }
    }

    // --- epilogue: BN (eval) + ReLU + store ---
    float* ob = out + (size_t)b * out_nch * IMG + (size_t)ochoff * IMG;
    #pragma unroll
    for (int p = 0; p < T; p++) {
        const int y = gy0 + y0 + p;
        const int x = gx0 + xl;
        float* op = ob + y * HW + x;
        #pragma unroll
        for (int u = 0; u < U2; u++) {
            float2 a = unpack2(acc[p][u]);
            int o0 = 2 * u, o1 = 2 * u + 1;
            float r0 = fmaf(a.x, s_sc[o0], s_bi[o0]);
            float r1 = fmaf(a.y, s_sc[o1], s_bi[o1]);
            op[(size_t)o0 * IMG] = fmaxf(r0, 0.f);
            op[(size_t)o1 * IMG] = fmaxf(r1, 0.f);
        }
    }
}

// ---------------------------------------------------------------------------
// Copy x into channels 12..21 of bufA (makes the dense-skip concat free).
// ---------------------------------------------------------------------------
__global__ void copy_x_kernel(const float* __restrict__ x, float* __restrict__ bufA)
{
    size_t idx = (size_t)blockIdx.x * blockDim.x + threadIdx.x;
    const size_t total = (size_t)NB * 10 * IMG;
    if (idx < total) {
        int p = (int)(idx % IMG);
        int c = (int)((idx / IMG) % 10);
        int b = (int)(idx / ((size_t)IMG * 10));
        bufA[((size_t)b * 22 + 12 + c) * IMG + p] = x[idx];
    }
}

// ---------------------------------------------------------------------------
// Final per-sample 1x1 conv: [B,22,H,W] x [B,11,22] -> [B,11,H,W]
// ---------------------------------------------------------------------------
__global__ __launch_bounds__(256)
void conv1x1_kernel(const float* __restrict__ in, const float* __restrict__ w4,
                    float* __restrict__ out)
{
    __shared__ float s_w[11 * 22];
    const int b   = blockIdx.y;
    const int tid = threadIdx.x;
    if (tid < 242) s_w[tid] = w4[b * 242 + tid];
    __syncthreads();

    const int p0 = blockIdx.x * (256 * 4) + tid;
    const float* inb = in  + (size_t)b * 22 * IMG;
    float*       ob  = out + (size_t)b * 11 * IMG;

    float acc[4][11];
    #pragma unroll
    for (int q = 0; q < 4; q++)
        #pragma unroll
        for (int o = 0; o < 11; o++) acc[q][o] = 0.f;

    #pragma unroll 2
    for (int i = 0; i < 22; i++) {
        float v[4];
        #pragma unroll
        for (int q = 0; q < 4; q++) v[q] = inb[(size_t)i * IMG + p0 + q * 256];
        #pragma unroll
        for (int o = 0; o < 11; o++) {
            float w = s_w[o * 22 + i];
            #pragma unroll
            for (int q = 0; q < 4; q++) acc[q][o] = fmaf(v[q], w, acc[q][o]);
        }
    }
    #pragma unroll
    for (int o = 0; o < 11; o++)
        #pragma unroll
        for (int q = 0; q < 4; q++)
            ob[(size_t)o * IMG + p0 + q * 256] = acc[q][o];
}

// ---------------------------------------------------------------------------

static int smem_bytes(int cin) {
    int nch   = (cin > 12) ? 2 : 1;
    int chunk = cin / nch;
    return (chunk * 10 * 66 + cin * 9 * 12 + 24) * 4;
}

extern "C" void kernel_launch(void* const* d_in, const int* in_sizes, int n_in,
                              void* d_out, int out_size)
{
    const float* x   = (const float*)d_in[0];
    const float* w1  = (const float*)d_in[1];
    const float* w2  = (const float*)d_in[2];
    const float* w3  = (const float*)d_in[3];
    const float* w4  = (const float*)d_in[4];
    const float* gam = (const float*)d_in[5];
    const float* bet = (const float*)d_in[6];
    const float* mea = (const float*)d_in[7];
    const float* var = (const float*)d_in[8];
    float* out = (float*)d_out;

    float *bufA, *bufB, *bufC;
    cudaGetSymbolAddress((void**)&bufA, g_bufA);
    cudaGetSymbolAddress((void**)&bufB, g_bufB);
    cudaGetSymbolAddress((void**)&bufC, g_bufC);

    // opt-in to >48KB dynamic smem (idempotent; host-side, capture-safe)
    cudaFuncSetAttribute(conv3x3_bn_relu12<10,1>, cudaFuncAttributeMaxDynamicSharedMemorySize, smem_bytes(10));
    cudaFuncSetAttribute(conv3x3_bn_relu12<12,1>, cudaFuncAttributeMaxDynamicSharedMemorySize, smem_bytes(12));
    cudaFuncSetAttribute(conv3x3_bn_relu12<22,2>, cudaFuncAttributeMaxDynamicSharedMemorySize, smem_bytes(22));
    cudaFuncSetAttribute(conv3x3_bn_relu12<24,2>, cudaFuncAttributeMaxDynamicSharedMemorySize, smem_bytes(24));
    cudaFuncSetAttribute(conv3x3_bn_relu12<24,1>, cudaFuncAttributeMaxDynamicSharedMemorySize, smem_bytes(24));

    const dim3 g1(2, 16, NB);   // 12-out layers: 2 x-tiles, 16 y-tiles
    const dim3 g2(4, 16, NB);   // 24-out layers: 2 x-tiles * 2 output halves

    // x -> bufA channels 12..21 (skip-concat source, written once per launch)
    copy_x_kernel<<<(NB * 10 * IMG + 255) / 256, 256>>>(x, bufA);

    // ---- stage 1 ----  (BN offsets: 0,12,24)
    conv3x3_bn_relu12<10,1><<<g1, 128, smem_bytes(10)>>>(x,    10, w1, 3672,    0, gam,bet,mea,var,   0, bufB, 24);
    conv3x3_bn_relu12<12,1><<<g1, 128, smem_bytes(12)>>>(bufB, 24, w1, 3672, 1080, gam,bet,mea,var,  12, bufC, 24);
    conv3x3_bn_relu12<12,1><<<g1, 128, smem_bytes(12)>>>(bufC, 24, w1, 3672, 2376, gam,bet,mea,var,  24, bufA, 22);
    // ---- stage 2 ----  (BN offsets: 36,60,84)
    conv3x3_bn_relu12<22,2><<<g2, 128, smem_bytes(22)>>>(bufA, 22, w2, 12528,    0, gam,bet,mea,var,  36, bufB, 24);
    conv3x3_bn_relu12<24,2><<<g2, 128, smem_bytes(24)>>>(bufB, 24, w2, 12528, 4752, gam,bet,mea,var,  60, bufC, 24);
    conv3x3_bn_relu12<24,1><<<g1, 128, smem_bytes(24)>>>(bufC, 24, w2, 12528, 9936, gam,bet,mea,var,  84, bufA, 22);
    // ---- stage 3 ----  (BN offsets: 96,120,144)
    conv3x3_bn_relu12<22,2><<<g2, 128, smem_bytes(22)>>>(bufA, 22, w3, 12528,    0, gam,bet,mea,var,  96, bufB, 24);
    conv3x3_bn_relu12<24,2><<<g2, 128, smem_bytes(24)>>>(bufB, 24, w3, 12528, 4752, gam,bet,mea,var, 120, bufC, 24);
    conv3x3_bn_relu12<24,1><<<g1, 128, smem_bytes(24)>>>(bufC, 24, w3, 12528, 9936, gam,bet,mea,var, 144, bufA, 22);
    // ---- stage 4: 1x1 predictor ----
    conv1x1_kernel<<<dim3(IMG / (256 * 4), NB), 256>>>(bufA, w4, out);
}